// round 15
// baseline (speedup 1.0000x reference)
#include <cuda_runtime.h>
#include <cuda_bf16.h>
#include <cuda_fp16.h>
#include <math.h>
#include <stddef.h>
#include <stdint.h>

// Problem constants
#define B_  8
#define S_  1024
#define C_  1024
#define H_  16
#define D_  64
#define M_TOT (B_ * S_)          // 8192
#define KV_N  (2 * C_)           // 2048
#define KC    C_                 // 1024

// sqrt(0.125 * log2(e)) — folded into K so S-MMA yields exp2-domain scores
#define KSCALE 0.42466089f

// Scratch (device globals; no runtime allocation allowed)
__device__ __half g_Kh[(size_t)B_ * H_ * S_ * D_];          // K fp16 (pre-scaled)
__device__ __half g_V16[(size_t)B_ * H_ * S_ * D_];         // V fp16
__device__ __half g_A2 [(size_t)M_TOT * KC];                // x fp16
__device__ __half g_B2 [(size_t)KV_N  * KC];                // Wqkv_kv^T fp16
__device__ __half g_A2p[(size_t)M_TOT * KC];                // attn out fp16
__device__ __half g_B2p[(size_t)C_    * KC];                // Wproj^T fp16

// ---------------------------------------------------------------------------
// PTX helpers (base-sm_100-legal)
// ---------------------------------------------------------------------------
__device__ __forceinline__ uint32_t smem_u32(const void* p) {
    uint32_t a;
    asm("{ .reg .u64 t; cvta.to.shared.u64 t, %1; cvt.u32.u64 %0, t; }" : "=r"(a) : "l"(p));
    return a;
}
__device__ __forceinline__ void cpasync16(uint32_t saddr, const void* g) {
    asm volatile("cp.async.cg.shared.global [%0], [%1], 16;" :: "r"(saddr), "l"(g) : "memory");
}
#define CP_COMMIT() asm volatile("cp.async.commit_group;" ::: "memory")
#define CP_WAIT(n)  asm volatile("cp.async.wait_group %0;" :: "n"(n) : "memory")

__device__ __forceinline__ void ldsm4(uint32_t* r, uint32_t addr) {
    asm volatile("ldmatrix.sync.aligned.m8n8.x4.shared.b16 {%0,%1,%2,%3}, [%4];"
                 : "=r"(r[0]), "=r"(r[1]), "=r"(r[2]), "=r"(r[3]) : "r"(addr));
}
__device__ __forceinline__ void ldsm4t(uint32_t* r, uint32_t addr) {
    asm volatile("ldmatrix.sync.aligned.m8n8.x4.trans.shared.b16 {%0,%1,%2,%3}, [%4];"
                 : "=r"(r[0]), "=r"(r[1]), "=r"(r[2]), "=r"(r[3]) : "r"(addr));
}
// fp16 MMA (all paths)
__device__ __forceinline__ void mma16816h(float* c, const uint32_t* a, const uint32_t* b) {
    asm volatile(
        "mma.sync.aligned.m16n8k16.row.col.f32.f16.f16.f32 "
        "{%0,%1,%2,%3}, {%4,%5,%6,%7}, {%8,%9}, {%0,%1,%2,%3};"
        : "+f"(c[0]), "+f"(c[1]), "+f"(c[2]), "+f"(c[3])
        : "r"(a[0]), "r"(a[1]), "r"(a[2]), "r"(a[3]), "r"(b[0]), "r"(b[1]));
}

// Swizzled smem offset for [rows][128B] tiles: 16B chunk c (0..7), 8-way XOR.
__device__ __forceinline__ uint32_t toff(int r, int c) {
    return (uint32_t)(r * 128 + (((c) ^ (r & 7)) << 4));
}
__device__ __forceinline__ uint32_t pack_h2(float a, float b) {
    __half2 h = __floats2half2_rn(a, b);
    return *(uint32_t*)&h;
}

// ---------------------------------------------------------------------------
// fp16 GEMM:  C = A2 @ B2^T + bias.  K=1024, BK=64 (16 stages).
// 256 threads, 8 warps of 64x32. 3-stage cp.async; prefetch issued BEFORE
// the MMA body so loads get maximal flight time.
// mode 0: epilogue scatters K (scaled fp16) and V (fp16).
// mode 1: writes fp32 out[m*1024+n].
// ---------------------------------------------------------------------------
#define NSTAGE (KC / 64)          // 16
#define GSTAGE_B 32768            // A 16K + B 16K per stage (128 rows x 128B)
#define GEMM_SMEM (3 * GSTAGE_B)  // 98304

__device__ __forceinline__ void gemm_load_stage(
    const __half* __restrict__ Ag, const __half* __restrict__ Bg,
    int kb, uint32_t Ab, uint32_t Bb, int tid)
{
#pragma unroll
    for (int i = 0; i < 4; i++) {
        const int idx = tid + i * 256;           // 0..1023
        const int r = idx >> 3, c = idx & 7;     // row 0..127, chunk 0..7
        const size_t g = (size_t)r * KC + kb * 64 + c * 8;
        const uint32_t so = toff(r, c);
        cpasync16(Ab + so, Ag + g);
        cpasync16(Bb + so, Bg + g);
    }
}

__global__ __launch_bounds__(256) void gemm_fp16_kernel(
    const __half* __restrict__ Ag, const __half* __restrict__ Bg,
    const float* __restrict__ bias, float* __restrict__ out, int mode)
{
    extern __shared__ __align__(1024) uint8_t gsm[];
    const uint32_t smb = smem_u32(gsm);

    const int tid  = threadIdx.x;
    const int lane = tid & 31;
    const int wid  = tid >> 5;
    const int wm = (wid >> 2) * 64;
    const int wn = (wid & 3) * 32;
    const int bn = blockIdx.x, bm = blockIdx.y;

    const __half* Arow = Ag + (size_t)(bm * 128) * KC;
    const __half* Brow = Bg + (size_t)(bn * 128) * KC;

    float acc[4][4][4];
#pragma unroll
    for (int f = 0; f < 4; f++)
#pragma unroll
        for (int g = 0; g < 4; g++)
#pragma unroll
            for (int r = 0; r < 4; r++) acc[f][g][r] = 0.0f;

    // prologue: prefetch stages 0 and 1
    gemm_load_stage(Arow, Brow, 0, smb, smb + 16384, tid);
    CP_COMMIT();
    gemm_load_stage(Arow, Brow, 1, smb + GSTAGE_B, smb + GSTAGE_B + 16384, tid);
    CP_COMMIT();

    int buf = 0, pbuf = 2;
    for (int kb = 0; kb < NSTAGE; kb++) {
        CP_WAIT(1);          // stage kb landed (only kb+1 may remain in flight)
        __syncthreads();     // pbuf (stage kb-1's buffer) now free CTA-wide

        // issue stage kb+2 prefetch FIRST — maximal load flight time
        if (kb + 2 < NSTAGE) {
            gemm_load_stage(Arow, Brow, kb + 2,
                            smb + pbuf * GSTAGE_B, smb + pbuf * GSTAGE_B + 16384, tid);
        }
        CP_COMMIT();

        const uint32_t Ab = smb + buf * GSTAGE_B;
        const uint32_t Bb = Ab + 16384;
#pragma unroll
        for (int ks = 0; ks < 4; ks++) {
            uint32_t a[4][4], b[4][2];
            const int ar = lane & 15;
            const int ac = ks * 2 + (lane >> 4);
#pragma unroll
            for (int f = 0; f < 4; f++)
                ldsm4(a[f], Ab + toff(wm + f * 16 + ar, ac));

            const int br = (lane & 7) + ((lane >> 4) << 3);
            const int bc = ks * 2 + ((lane >> 3) & 1);
#pragma unroll
            for (int p = 0; p < 2; p++) {
                uint32_t r4[4];
                ldsm4(r4, Bb + toff(wn + p * 16 + br, bc));
                b[2 * p][0] = r4[0]; b[2 * p][1] = r4[1];
                b[2 * p + 1][0] = r4[2]; b[2 * p + 1][1] = r4[3];
            }
#pragma unroll
            for (int f = 0; f < 4; f++)
#pragma unroll
                for (int g = 0; g < 4; g++)
                    mma16816h(acc[f][g], a[f], b[g]);
        }

        buf = (buf == 2) ? 0 : buf + 1;
        pbuf = (pbuf == 2) ? 0 : pbuf + 1;
    }

    const int gr = lane >> 2;
    const int tcol = (lane & 3) * 2;
#pragma unroll
    for (int f = 0; f < 4; f++) {
        const int r0 = bm * 128 + wm + f * 16 + gr;
        const int b_ = r0 >> 10, s_ = r0 & 1023;
        const int r1 = r0 + 8;
        const int b1_ = r1 >> 10, s1_ = r1 & 1023;
#pragma unroll
        for (int g = 0; g < 4; g++) {
            const int cc = wn + g * 8 + tcol;
            const int n = bn * 128 + cc;
            const float bx = bias[n], by = bias[n + 1];
            float2 v0 = make_float2(acc[f][g][0] + bx, acc[f][g][1] + by);
            float2 v1 = make_float2(acc[f][g][2] + bx, acc[f][g][3] + by);
            if (mode == 0) {
                const int np = n & (C_ - 1);
                const int hh = np >> 6, dd = np & 63;
                const size_t o0 = (((size_t)(b_  * H_ + hh)) * S_ + s_ ) * D_ + dd;
                const size_t o1 = (((size_t)(b1_ * H_ + hh)) * S_ + s1_) * D_ + dd;
                if (n < C_) {   // K: scale, plain fp16
                    *(uint32_t*)&g_Kh[o0] = pack_h2(v0.x * KSCALE, v0.y * KSCALE);
                    *(uint32_t*)&g_Kh[o1] = pack_h2(v1.x * KSCALE, v1.y * KSCALE);
                } else {        // V: plain fp16
                    *(uint32_t*)&g_V16[o0] = pack_h2(v0.x, v0.y);
                    *(uint32_t*)&g_V16[o1] = pack_h2(v1.x, v1.y);
                }
            } else {
                *(float2*)&out[(size_t)r0 * C_ + n] = v0;
                *(float2*)&out[(size_t)r1 * C_ + n] = v1;
            }
        }
    }
}

// ---------------------------------------------------------------------------
// cvt_x: x fp32 [8192][1024] -> g_A2 fp16 [8192][1024]
// ---------------------------------------------------------------------------
__global__ __launch_bounds__(256) void cvt_x_kernel(const float* __restrict__ x)
{
    const int idx = blockIdx.x * 256 + threadIdx.x;
    const int m = idx >> 8;
    const int k = (idx & 255) << 2;
    const float4 v = *(const float4*)&x[(size_t)m * C_ + k];
    __half* row = g_A2 + (size_t)m * KC;
    *(uint32_t*)(row + k)     = pack_h2(v.x, v.y);
    *(uint32_t*)(row + k + 2) = pack_h2(v.z, v.w);
}

// ---------------------------------------------------------------------------
// tcvt: both weight transposes in ONE launch.
// blockIdx.y < 64: Wqkv[:,1024:] (ld 3072) -> g_B2 [2048][1024]
// else:            Wproj (ld 1024)        -> g_B2p [1024][1024]
// ---------------------------------------------------------------------------
__global__ __launch_bounds__(256) void tcvt_kernel(
    const float* __restrict__ wqkv, const float* __restrict__ wproj)
{
    __shared__ float t[32][33];
    const bool second = (blockIdx.y >= 64);
    const int  ny = second ? (blockIdx.y - 64) : blockIdx.y;
    const float* src = second ? wproj : (wqkv + C_);
    __half* dst = second ? g_B2p : g_B2;
    const int srcld = second ? C_ : 3 * C_;

    const int n0 = ny * 32, k0 = blockIdx.x * 32;
    const int tx = threadIdx.x & 31, ty = threadIdx.x >> 5;
#pragma unroll
    for (int i = 0; i < 4; i++)
        t[ty + i * 8][tx] = src[(size_t)(k0 + ty + i * 8) * srcld + n0 + tx];
    __syncthreads();
#pragma unroll
    for (int i = 0; i < 4; i++) {
        const int n = n0 + ty + i * 8;
        const int k = k0 + tx;
        dst[(size_t)n * KC + k] = __float2half_rn(t[tx][ty + i * 8]);
    }
}

// ---------------------------------------------------------------------------
// MMA flash attention. S path: 1-term fp16. PV: 1-term fp16.
// qt reversed; 5 CTAs/SM (smem 40KB, regs capped at 102).
// smem: Q 8K + 2 stages x (Kh 8K | V16 8K).
// ---------------------------------------------------------------------------
#define STAGE_B 16384
#define SM_Q    0
#define SM_STG  8192
#define ATT_SMEM (8192 + 2 * STAGE_B)      // 40960

__device__ __forceinline__ void att_load_tile(
    uint32_t dst, const __half* Kh, const __half* V16, int jt, int tid)
{
    const size_t gb = (size_t)jt * 8192;
#pragma unroll
    for (int i = 0; i < 4; i++) {
        const int idx = tid + i * 128;
        const int r = idx >> 3, c = idx & 7;
        const uint32_t so = toff(r, c);
        const size_t go = gb + (size_t)r * 128 + c * 16;
        cpasync16(dst +        so, (const char*)Kh  + go);
        cpasync16(dst + 8192 + so, (const char*)V16 + go);
    }
}

__global__ __launch_bounds__(128, 5) void attn_mma_kernel()
{
    extern __shared__ uint8_t asmem[];
    const uint32_t smb = smem_u32(asmem);
    const int tid = threadIdx.x, lane = tid & 31, w = tid >> 5;
    const int qt = (S_ / 64 - 1) - blockIdx.x;   // long CTAs launch first
    const int bh = blockIdx.y;
    const int gr = lane >> 2, tq = lane & 3;

    const __half* Kh  = g_Kh + (size_t)bh * S_ * D_;
    const __half* V16 = g_V16 + (size_t)bh * S_ * D_;

    {
        const size_t gb = (size_t)qt * 8192;
#pragma unroll
        for (int i = 0; i < 4; i++) {
            const int idx = tid + i * 128;
            const int r = idx >> 3, c = idx & 7;
            cpasync16(smb + SM_Q + toff(r, c),
                      (const char*)Kh + gb + (size_t)r * 128 + c * 16);
        }
        CP_COMMIT();
        att_load_tile(smb + SM_STG, Kh, V16, 0, tid);
        CP_COMMIT();
    }

    uint32_t qh[4][4];
    float o[8][4];
#pragma unroll
    for (int g = 0; g < 8; g++)
#pragma unroll
        for (int r = 0; r < 4; r++) o[g][r] = 0.0f;
    float mrow0 = -1e30f, mrow1 = -1e30f, lrow0 = 0.0f, lrow1 = 0.0f;

    const int ar = lane & 15, hc = lane >> 4;
    const int br = (lane & 7) + ((lane >> 4) << 3);
    const int bcs = (lane >> 3) & 1;
    const int vr = (lane & 7) + (((lane >> 3) & 1) << 3);
    const int vcs = lane >> 4;

    for (int jt = 0; jt <= qt; jt++) {
        const uint32_t Kb = smb + SM_STG + (jt & 1) * STAGE_B;
        if (jt < qt) {
            att_load_tile(smb + SM_STG + ((jt + 1) & 1) * STAGE_B,
                          Kh, V16, jt + 1, tid);
            CP_COMMIT();
            CP_WAIT(1);
        } else {
            CP_WAIT(0);
        }
        __syncthreads();

        if (jt == 0) {
#pragma unroll
            for (int ks = 0; ks < 4; ks++)
                ldsm4(qh[ks], smb + SM_Q + toff(16 * w + ar, 2 * ks + hc));
        }

        // S = Q K^T (fp16 1-term)
        float s[8][4];
#pragma unroll
        for (int g = 0; g < 8; g++)
#pragma unroll
            for (int r = 0; r < 4; r++) s[g][r] = 0.0f;
#pragma unroll
        for (int ks = 0; ks < 4; ks++) {
#pragma unroll
            for (int p = 0; p < 4; p++) {
                uint32_t kh4[4];
                ldsm4(kh4, Kb + toff(16 * p + br, 2 * ks + bcs));
                mma16816h(s[2 * p],     qh[ks], kh4);
                mma16816h(s[2 * p + 1], qh[ks], kh4 + 2);
            }
        }

        if (jt == qt) {
            const int rb = 16 * w + gr;
#pragma unroll
            for (int g = 0; g < 8; g++) {
                const int c0 = 8 * g + 2 * tq;
                if (c0     > rb)     s[g][0] = -1e30f;
                if (c0 + 1 > rb)     s[g][1] = -1e30f;
                if (c0     > rb + 8) s[g][2] = -1e30f;
                if (c0 + 1 > rb + 8) s[g][3] = -1e30f;
            }
        }

        float mx0 = -1e30f, mx1 = -1e30f;
#pragma unroll
        for (int g = 0; g < 8; g++) {
            mx0 = fmaxf(mx0, fmaxf(s[g][0], s[g][1]));
            mx1 = fmaxf(mx1, fmaxf(s[g][2], s[g][3]));
        }
        mx0 = fmaxf(mx0, __shfl_xor_sync(0xffffffffu, mx0, 1));
        mx0 = fmaxf(mx0, __shfl_xor_sync(0xffffffffu, mx0, 2));
        mx1 = fmaxf(mx1, __shfl_xor_sync(0xffffffffu, mx1, 1));
        mx1 = fmaxf(mx1, __shfl_xor_sync(0xffffffffu, mx1, 2));
        const float mn0 = fmaxf(mrow0, mx0), mn1 = fmaxf(mrow1, mx1);
        const float a0 = exp2f(mrow0 - mn0), a1 = exp2f(mrow1 - mn1);
        mrow0 = mn0; mrow1 = mn1;
        float sum0 = 0.0f, sum1 = 0.0f;
#pragma unroll
        for (int g = 0; g < 8; g++) {
            s[g][0] = exp2f(s[g][0] - mn0); sum0 += s[g][0];
            s[g][1] = exp2f(s[g][1] - mn0); sum0 += s[g][1];
            s[g][2] = exp2f(s[g][2] - mn1); sum1 += s[g][2];
            s[g][3] = exp2f(s[g][3] - mn1); sum1 += s[g][3];
        }
        sum0 += __shfl_xor_sync(0xffffffffu, sum0, 1);
        sum0 += __shfl_xor_sync(0xffffffffu, sum0, 2);
        sum1 += __shfl_xor_sync(0xffffffffu, sum1, 1);
        sum1 += __shfl_xor_sync(0xffffffffu, sum1, 2);
        lrow0 = lrow0 * a0 + sum0;
        lrow1 = lrow1 * a1 + sum1;
#pragma unroll
        for (int g = 0; g < 8; g++) {
            o[g][0] *= a0; o[g][1] *= a0; o[g][2] *= a1; o[g][3] *= a1;
        }

        // O += P V  (single-term fp16)
#pragma unroll
        for (int ks = 0; ks < 4; ks++) {
            uint32_t ph[4];
            ph[0] = pack_h2(s[2 * ks][0],     s[2 * ks][1]);
            ph[1] = pack_h2(s[2 * ks][2],     s[2 * ks][3]);
            ph[2] = pack_h2(s[2 * ks + 1][0], s[2 * ks + 1][1]);
            ph[3] = pack_h2(s[2 * ks + 1][2], s[2 * ks + 1][3]);
#pragma unroll
            for (int p2 = 0; p2 < 4; p2++) {
                uint32_t vh4[4];
                ldsm4t(vh4, Kb + 8192 + toff(16 * ks + vr, 2 * p2 + vcs));
                mma16816h(o[2 * p2],     ph, vh4);
                mma16816h(o[2 * p2 + 1], ph, vh4 + 2);
            }
        }
        __syncthreads();
    }

    // Epilogue: normalize, write plain fp16 rows into g_A2p
    const float i0 = 1.0f / lrow0, i1 = 1.0f / lrow1;
    const int b = bh >> 4, h = bh & 15;
    const int r0 = qt * 64 + 16 * w + gr;
    const int r1 = r0 + 8;
    __half* row0 = g_A2p + (size_t)(b * S_ + r0) * KC + h * 64;
    __half* row1 = g_A2p + (size_t)(b * S_ + r1) * KC + h * 64;
#pragma unroll
    for (int g = 0; g < 8; g++) {
        const int d = 8 * g + 2 * tq;
        *(uint32_t*)(row0 + d) = pack_h2(o[g][0] * i0, o[g][1] * i0);
        *(uint32_t*)(row1 + d) = pack_h2(o[g][2] * i1, o[g][3] * i1);
    }
}

// ---------------------------------------------------------------------------
extern "C" void kernel_launch(void* const* d_in, const int* in_sizes, int n_in,
                              void* d_out, int out_size)
{
    const float* x     = (const float*)d_in[0];
    const float* Wqkv  = (const float*)d_in[1];
    const float* bqkv  = (const float*)d_in[2];
    const float* Wproj = (const float*)d_in[3];
    const float* bproj = (const float*)d_in[4];
    float* out = (float*)d_out;

    __half *a2, *b2, *a2p, *b2p;
    cudaGetSymbolAddress((void**)&a2,  g_A2);
    cudaGetSymbolAddress((void**)&b2,  g_B2);
    cudaGetSymbolAddress((void**)&a2p, g_A2p);
    cudaGetSymbolAddress((void**)&b2p, g_B2p);

    // Phase 0: fp16 conversion + fused weight transposes
    cvt_x_kernel<<<M_TOT, 256>>>(x);
    tcvt_kernel<<<dim3(C_ / 32, 96), 256>>>(Wqkv, Wproj);

    cudaFuncSetAttribute(gemm_fp16_kernel,
                         cudaFuncAttributeMaxDynamicSharedMemorySize,
                         GEMM_SMEM);

    // Phase 1: KV projection (fp16 tensor GEMM, K=1024, BK=64)
    {
        dim3 grid(KV_N / 128, M_TOT / 128);   // (16, 64)
        gemm_fp16_kernel<<<grid, 256, GEMM_SMEM>>>(a2, b2, bqkv + C_, nullptr, 0);
    }

    // Phase 2: causal attention on mma.sync (q = k), 64-key tiles
    {
        cudaFuncSetAttribute(attn_mma_kernel,
                             cudaFuncAttributeMaxDynamicSharedMemorySize,
                             ATT_SMEM);
        dim3 grid(S_ / 64, B_ * H_);          // (16, 128)
        attn_mma_kernel<<<grid, 128, ATT_SMEM>>>();
    }

    // Phase 3: output projection (fp16 tensor GEMM, K=1024, BK=64)
    {
        dim3 grid(C_ / 128, M_TOT / 128);     // (8, 64)
        gemm_fp16_kernel<<<grid, 256, GEMM_SMEM>>>(a2p, b2p, bproj, out, 1);
    }
}